// round 14
// baseline (speedup 1.0000x reference)
#include <cuda_runtime.h>
#include <cuda_bf16.h>
#include <cuda_fp16.h>
#include <mma.h>
using namespace nvcuda;

#define NN  512
#define BSZ 64
#define TT  200

#define QM4  2560.0f
#define QL0  7.0f
#define QL1  127.0f

static constexpr size_t MAT = (size_t)BSZ * NN * NN;
__device__ __nv_bfloat16 g_P[MAT];
__device__ __nv_bfloat16 g_Q[MAT];
__device__ unsigned char g_MQ[(size_t)BSZ * NN * 256];      // int4-packed M^T
__device__ float2 g_XE[(size_t)BSZ * (TT - 1) * NN];        // (base, E) per step
__device__ float  g_LP0[(size_t)BSZ * NN];                  // initial last_perf

// ---------------------------------------------------------------------------
__global__ void k_convert(const float* __restrict__ adj, __nv_bfloat16* __restrict__ P) {
    size_t i = ((size_t)blockIdx.x * blockDim.x + threadIdx.x) * 4;
    float4 v = *(const float4*)(adj + i);
    const float s = 1.0f / 512.0f;
    __nv_bfloat162 p0 = __floats2bfloat162_rn(v.x * s, v.y * s);
    __nv_bfloat162 p1 = __floats2bfloat162_rn(v.z * s, v.w * s);
    uint2 u; u.x = *(unsigned*)&p0; u.y = *(unsigned*)&p1;
    *(uint2*)(P + i) = u;
}

__device__ __forceinline__ float2 bf2f2(unsigned u) {
    __nv_bfloat162 h = *(__nv_bfloat162*)&u;
    return make_float2(__low2float(h), __high2float(h));
}

__device__ __forceinline__ void cp16(void* s, const void* g) {
    unsigned sa = (unsigned)__cvta_generic_to_shared(s);
    asm volatile("cp.async.cg.shared.global [%0], [%1], 16;\n" :: "r"(sa), "l"(g));
}

// Batched bf16 GEMM (R12 config): 256 threads, 3-stage cp.async, padded smem.
#define AST 72
#define BST 136
#define A_ELL (128 * AST)
#define B_ELL (64 * BST)
#define STG_ELL (A_ELL + B_ELL)
#define GEMM_SMEM (3 * STG_ELL * 2)

__global__ void __launch_bounds__(256) k_gemm(const __nv_bfloat16* __restrict__ A,
                                              const __nv_bfloat16* __restrict__ B,
                                              __nv_bfloat16* __restrict__ C,
                                              const __nv_bfloat16* __restrict__ addA,
                                              const __nv_bfloat16* __restrict__ addB,
                                              unsigned char* __restrict__ qOut) {
    extern __shared__ __nv_bfloat16 smg[];
    const int tid = threadIdx.x, b = blockIdx.z;
    const int bm0 = blockIdx.y * 128, bn0 = blockIdx.x * 128;
    const __nv_bfloat16* Ab = A + (size_t)b * NN * NN;
    const __nv_bfloat16* Bb = B + (size_t)b * NN * NN;
    const int ar = tid >> 3, ac = (tid & 7) * 8;
    const int br = tid >> 4, bc = (tid & 15) * 8;
    auto load_tiles = [&](int st, int k0) {
        __nv_bfloat16* a  = smg + st * STG_ELL;
        __nv_bfloat16* bt = smg + st * STG_ELL + A_ELL;
#pragma unroll
        for (int rr = 0; rr < 128; rr += 32)
            cp16(a + (ar + rr) * AST + ac, Ab + (size_t)(bm0 + ar + rr) * NN + k0 + ac);
#pragma unroll
        for (int rr = 0; rr < 64; rr += 16)
            cp16(bt + (br + rr) * BST + bc, Bb + (size_t)(k0 + br + rr) * NN + bn0 + bc);
        asm volatile("cp.async.commit_group;\n");
    };
    const int w = tid >> 5, wm = w >> 1, wn = w & 1;
    wmma::fragment<wmma::accumulator, 16, 16, 16, float> cf[2][4];
#pragma unroll
    for (int i = 0; i < 2; i++)
#pragma unroll
        for (int j = 0; j < 4; j++) wmma::fill_fragment(cf[i][j], 0.0f);
    load_tiles(0, 0);
    load_tiles(1, 64);
#pragma unroll
    for (int kt = 0; kt < 8; ++kt) {
        if (kt < 6) asm volatile("cp.async.wait_group 1;\n");
        else        asm volatile("cp.async.wait_group 0;\n");
        __syncthreads();
        if (kt < 6) load_tiles((kt + 2) % 3, (kt + 2) * 64);
        const __nv_bfloat16* a  = smg + (kt % 3) * STG_ELL;
        const __nv_bfloat16* bt = smg + (kt % 3) * STG_ELL + A_ELL;
#pragma unroll
        for (int kk = 0; kk < 4; ++kk) {
            wmma::fragment<wmma::matrix_a, 16, 16, 16, __nv_bfloat16, wmma::row_major> af[2];
            wmma::fragment<wmma::matrix_b, 16, 16, 16, __nv_bfloat16, wmma::row_major> bfr[4];
#pragma unroll
            for (int i = 0; i < 2; i++)
                wmma::load_matrix_sync(af[i], a + (wm * 32 + i * 16) * AST + kk * 16, AST);
#pragma unroll
            for (int j = 0; j < 4; j++)
                wmma::load_matrix_sync(bfr[j], bt + (kk * 16) * BST + wn * 64 + j * 16, BST);
#pragma unroll
            for (int i = 0; i < 2; i++)
#pragma unroll
                for (int j = 0; j < 4; j++)
                    wmma::mma_sync(cf[i][j], af[i], bfr[j], cf[i][j]);
        }
    }
    __syncthreads();
    float* Cs = (float*)smg;
#pragma unroll
    for (int i = 0; i < 2; i++)
#pragma unroll
        for (int j = 0; j < 4; j++)
            wmma::store_matrix_sync(Cs + (wm * 32 + i * 16) * 132 + wn * 64 + j * 16,
                                    cf[i][j], 132, wmma::mem_row_major);
    __syncthreads();

    const int rl = tid >> 1, half = tid & 1;
    const size_t goff = (size_t)b * NN * NN + (size_t)(bm0 + rl) * NN + bn0 + half * 64;

    if (qOut == nullptr) {
        __nv_bfloat16* Cg = C + goff;
        const float* src = Cs + rl * 132 + half * 64;
#pragma unroll
        for (int c = 0; c < 64; c += 4) {
            float4 v = *(const float4*)(src + c);
            __nv_bfloat162 p0 = __floats2bfloat162_rn(v.x, v.y);
            __nv_bfloat162 p1 = __floats2bfloat162_rn(v.z, v.w);
            uint2 u; u.x = *(unsigned*)&p0; u.y = *(unsigned*)&p1;
            *(uint2*)(Cg + c) = u;
        }
        return;
    }

    {
        float* dst = Cs + rl * 132 + half * 64;
#pragma unroll
        for (int c = 0; c < 64; c += 4) {
            float4 v = *(const float4*)(dst + c);
            uint2 pa = *(const uint2*)(addA + goff + c);
            uint2 qa = *(const uint2*)(addB + goff + c);
            float2 a0 = bf2f2(pa.x), a1 = bf2f2(pa.y);
            float2 b0 = bf2f2(qa.x), b1 = bf2f2(qa.y);
            v.x += a0.x + b0.x; v.y += a0.y + b0.y;
            v.z += a1.x + b1.x; v.w += a1.y + b1.y;
            *(float4*)(dst + c) = v;
        }
    }
    __syncthreads();
    {
        const int kr = tid >> 1;
        const int jh = (tid & 1) * 32;
        unsigned char bytes[32];
#pragma unroll
        for (int jj = 0; jj < 32; ++jj) {
            const int jp = jh + jj;
            float v0 = Cs[(2 * jp) * 132 + kr];
            float v1 = Cs[(2 * jp + 1) * 132 + kr];
            int q0 = min(15, max(0, __float2int_rn(v0 * QM4)));
            int q1 = min(15, max(0, __float2int_rn(v1 * QM4)));
            bytes[jj] = (unsigned char)(q0 | (q1 << 4));
        }
        unsigned char* dst = qOut + (size_t)b * (NN * 256) + (size_t)(bn0 + kr) * 256 + (bm0 >> 1) + jh;
        *(uint4*)(dst)      = *(uint4*)(bytes);
        *(uint4*)(dst + 16) = *(uint4*)(bytes + 16);
    }
}

// ---------------------------------------------------------------------------
// k_pre: per-batch (ub, uf) MLP recurrence + base/nlf dots + temporal factor,
// for all 199 steps. Output: g_XE[(b*199+s)*512+k] = (base, E), g_LP0.
// 64 CTAs x 512 threads. Thread k = tid owns node k (emb in regs).
// ---------------------------------------------------------------------------
#define BAR1() asm volatile("bar.sync 1, 128;" ::: "memory")

__global__ void __launch_bounds__(512, 1)
k_pre(const int* __restrict__ skills, const int* __restrict__ times_,
      const float* __restrict__ labels, const float* __restrict__ nemb,
      const float* __restrict__ ub0, const float* __restrict__ uf0,
      const float* __restrict__ cw1, const float* __restrict__ cb1,
      const float* __restrict__ cw2, const float* __restrict__ cb2,
      const float* __restrict__ lfw, const float* __restrict__ lfb,
      const float* __restrict__ lbw, const float* __restrict__ lbb,
      float2* __restrict__ XE, float* __restrict__ LP0) {

    __shared__ float w1t[160 * 32];
    __shared__ float w2t[32 * 32];
    __shared__ float wft[32 * 32];
    __shared__ float wbt[32 * 32];
    __shared__ float bias[128];
    __shared__ float ubuf[64], ufbuf[64];
    __shared__ float hbuf[32], uubuf[32], mlpp[128];
    __shared__ float skc[64];
    __shared__ float del_s[TT], lab_s[TT];
    __shared__ int   skl_s[TT];

    const int tid = threadIdx.x;
    const int b   = blockIdx.x;

    for (int i = tid; i < 5120; i += 512) { int o = i / 160, r = i % 160; w1t[r * 32 + o] = cw1[i]; }
    for (int i = tid; i < 1024; i += 512) {
        int o = i >> 5, r = i & 31;
        w2t[r * 32 + o] = cw2[i]; wft[r * 32 + o] = lfw[i]; wbt[r * 32 + o] = lbw[i];
    }
    if (tid < 32) {
        bias[tid] = cb1[tid]; bias[32 + tid] = cb2[tid];
        bias[64 + tid] = lfb[tid]; bias[96 + tid] = lbb[tid];
        ubuf[tid] = ub0[b * 32 + tid]; ufbuf[tid] = uf0[b * 32 + tid];
    }
    const float invlog5 = 0.6213349345596119f;
    for (int s = tid; s < TT - 1; s += 512) {
        float dtv = fabsf((float)(times_[b * TT + s + 1] - times_[b * TT + s]));
        del_s[s] = logf(dtv + 1e-6f) * invlog5;
        lab_s[s] = labels[b * TT + s + 1];
        skl_s[s] = skills[b * TT + s + 1];
    }

    // node embedding in regs (node k = tid)
    float nr[32], ns[32];
#pragma unroll
    for (int d = 0; d < 32; d++) {
        ns[d] = nemb[tid * 64 + d];
        nr[d] = nemb[tid * 64 + 32 + d];
    }
    __syncthreads();

    // init: lp0 + prev_nlf
    float prev_nlf;
    {
        float l0 = 0.f, n0 = 0.f;
#pragma unroll
        for (int d = 0; d < 32; d++) {
            l0 += ubuf[d] * nr[d];
            n0 += ufbuf[d] * ns[d];
        }
        LP0[b * NN + tid] = l0;
        prev_nlf = n0;
    }

    float2* xeB = XE + (size_t)b * (TT - 1) * NN + tid;

    for (int s = 0; s < TT - 1; ++s) {
        const int p = s & 1;
        const int skill = skl_s[s];

        // dots from current state
        float baseD = 0.f, nlfD = 0.f;
#pragma unroll
        for (int d = 0; d < 32; d++) {
            baseD += ubuf[p * 32 + d] * nr[d];
            nlfD  += ufbuf[p * 32 + d] * ns[d];
        }
        const float E = __expf(-del_s[s] * 0.1f * prev_nlf);
        xeB[(size_t)s * NN] = make_float2(baseD, E);
        prev_nlf = nlfD;

        // MLP on threads 0..127 (updates ubuf/ufbuf[p^1])
        if (tid < 128) {
            const int m = tid;
            const int o = m & 31;
            const float lab = lab_s[s];
            if (m < 64) skc[m] = __ldg(nemb + skill * 64 + m);
            BAR1();
            {
                const int q = m >> 5;
                float hp = 0.f;
#pragma unroll
                for (int cc = 0; cc < 8; cc++) {
                    const int c = q * 8 + cc;
                    const float u0 = ubuf[p * 32 + c], u1 = ufbuf[p * 32 + c];
                    const float u3 = skc[32 + c], u4 = skc[c];
                    const float* wv = w1t + c * 160 + o;
                    hp += u0 * wv[0] + u1 * wv[32] + lab * wv[64] + u3 * wv[96] + u4 * wv[128];
                }
                mlpp[q * 32 + o] = hp;
            }
            BAR1();
            if (m < 32) hbuf[o] = fmaxf(bias[o] + mlpp[o] + mlpp[32 + o] + mlpp[64 + o] + mlpp[96 + o], 0.f);
            BAR1();
            {
                const int q = m >> 5;
                float up = 0.f;
#pragma unroll
                for (int ii = 0; ii < 8; ii++) {
                    const int i2 = q * 8 + ii;
                    up += hbuf[i2] * w2t[i2 * 32 + o];
                }
                mlpp[q * 32 + o] = up;
            }
            BAR1();
            if (m < 32) uubuf[o] = bias[32 + o] + mlpp[o] + mlpp[32 + o] + mlpp[64 + o] + mlpp[96 + o];
            BAR1();
            {
                float ap = 0.f;
                if (m < 64) {
                    const int q2 = m >> 5;
#pragma unroll
                    for (int ii = 0; ii < 16; ii++) {
                        const int i2 = q2 * 16 + ii;
                        ap += uubuf[i2] * wft[i2 * 32 + o];
                    }
                    mlpp[q2 * 32 + o] = ap;
                } else {
                    const int q2 = (m - 64) >> 5;
#pragma unroll
                    for (int ii = 0; ii < 16; ii++) {
                        const int i2 = q2 * 16 + ii;
                        ap += uubuf[i2] * wbt[i2 * 32 + o];
                    }
                    mlpp[64 + q2 * 32 + o] = ap;
                }
            }
            BAR1();
            if (m < 32) {
                ufbuf[(p ^ 1) * 32 + o] = tanhf(bias[64 + o] + mlpp[o] + mlpp[32 + o]);
                ubuf[(p ^ 1) * 32 + o]  = tanhf(bias[96 + o] + mlpp[64 + o] + mlpp[96 + o]);
            }
        }
        __syncthreads();
    }
}

// ---------------------------------------------------------------------------
// Scan v5: 512 threads, M entirely in registers, (base, E) streamed from g_XE.
// Per step: sigmoid(x0 + E*lp + spatial) only.
// ---------------------------------------------------------------------------
__device__ __forceinline__ void dp4aUS(int& acc, unsigned a, unsigned b) {
    asm("dp4a.u32.s32 %0, %1, %2, %0;" : "+r"(acc) : "r"(a), "r"(b));
}

__global__ void __launch_bounds__(512, 1)
k_scan(const int* __restrict__ skills,
       const float2* __restrict__ XE, const float* __restrict__ LP0,
       const unsigned char* __restrict__ MQg, float* __restrict__ out) {

    __shared__ char lpq[2][512];
    __shared__ int  skl_s[TT];

    const int tid = threadIdx.x;
    const int b   = blockIdx.x;

    for (int s = tid; s < TT - 1; s += 512) skl_s[s] = skills[b * TT + s + 1];

    // M row (k = tid) fully in registers: 16 uint4 = 256 bytes
    uint4 Mr[16];
    {
        const uint4* mp = (const uint4*)(MQg + (size_t)b * (NN * 256) + (size_t)tid * 256);
#pragma unroll
        for (int i = 0; i < 16; i++) Mr[i] = __ldg(mp + i);
    }

    float lp_reg = LP0[b * NN + tid];
    {
        int q = __float2int_rn(lp_reg * QL0);
        q = max(min(q, 127), -127);
        lpq[0][(tid >> 1) + (tid & 1) * 256] = (char)q;
    }
    __syncthreads();

    const float INV0 = 1.0f / (QM4 * QL0 * 1536.0f);
    const float INV1 = 1.0f / (QM4 * QL1 * 1536.0f);

    const float2* xeB = XE + (size_t)b * (TT - 1) * NN + tid;
    float2 xe_n = __ldg(xeB);    // step 0

    for (int s = 0; s < TT - 1; ++s) {
        const int p = s & 1;
        const float2 xe = xe_n;
        if (s + 1 < TT - 1) xe_n = __ldg(xeB + (size_t)(s + 1) * NN);

        // int4 GEMV over all 512 j for k = tid (M in regs)
        int aL0 = 0, aL1 = 0, aH0 = 0, aH1 = 0;
        const uint4* le4 = (const uint4*)(lpq[p]);
        const uint4* lo4 = (const uint4*)(lpq[p] + 256);
#pragma unroll
        for (int i = 0; i < 16; i++) {
            uint4 m  = Mr[i];
            uint4 ea = le4[i];
            uint4 ob = lo4[i];
            dp4aUS(aL0, m.x & 0x0F0F0F0Fu, ea.x); dp4aUS(aH0, m.x & 0xF0F0F0F0u, ob.x);
            dp4aUS(aL1, m.y & 0x0F0F0F0Fu, ea.y); dp4aUS(aH1, m.y & 0xF0F0F0F0u, ob.y);
            dp4aUS(aL0, m.z & 0x0F0F0F0Fu, ea.z); dp4aUS(aH0, m.z & 0xF0F0F0F0u, ob.z);
            dp4aUS(aL1, m.w & 0x0F0F0F0Fu, ea.w); dp4aUS(aH1, m.w & 0xF0F0F0F0u, ob.w);
        }
        const int acc = (aL0 + aL1) + ((aH0 + aH1) >> 4);

        const float INVs = (s == 0) ? INV0 : INV1;
        const float x = xe.x + xe.y * lp_reg + (float)acc * INVs;
        const float cur = 1.0f / (1.0f + __expf(-x));
        lp_reg = cur;
        if (tid == skl_s[s]) out[s * BSZ + b] = cur;
        const int q8 = __float2int_rn(cur * QL1);
        lpq[p ^ 1][(tid >> 1) + (tid & 1) * 256] = (char)q8;
        __syncthreads();
    }
}

// ---------------------------------------------------------------------------
extern "C" void kernel_launch(void* const* d_in, const int* in_sizes, int n_in,
                              void* d_out, int out_size) {
    const int*   skills = (const int*)  d_in[0];
    const int*   times_ = (const int*)  d_in[1];
    const float* labels = (const float*)d_in[2];
    const float* adj    = (const float*)d_in[3];
    const float* nemb   = (const float*)d_in[4];
    const float* ub0    = (const float*)d_in[5];
    const float* uf0    = (const float*)d_in[6];
    const float* cw1    = (const float*)d_in[7];
    const float* cb1    = (const float*)d_in[8];
    const float* cw2    = (const float*)d_in[9];
    const float* cb2    = (const float*)d_in[10];
    const float* lfw    = (const float*)d_in[11];
    const float* lfb    = (const float*)d_in[12];
    const float* lbw    = (const float*)d_in[13];
    const float* lbb    = (const float*)d_in[14];

    void *pP = nullptr, *pQ = nullptr, *pMQ = nullptr, *pXE = nullptr, *pLP0 = nullptr;
    cudaGetSymbolAddress(&pP, g_P);
    cudaGetSymbolAddress(&pQ, g_Q);
    cudaGetSymbolAddress(&pMQ, g_MQ);
    cudaGetSymbolAddress(&pXE, g_XE);
    cudaGetSymbolAddress(&pLP0, g_LP0);
    __nv_bfloat16* P  = (__nv_bfloat16*)pP;
    __nv_bfloat16* Q  = (__nv_bfloat16*)pQ;
    unsigned char* MQ = (unsigned char*)pMQ;
    float2*        XE = (float2*)pXE;
    float*         LP = (float*)pLP0;

    cudaFuncSetAttribute(k_gemm, cudaFuncAttributeMaxDynamicSharedMemorySize, GEMM_SMEM);

    k_convert<<<16384, 256>>>(adj, P);
    k_pre<<<BSZ, 512>>>(skills, times_, labels, nemb, ub0, uf0,
                        cw1, cb1, cw2, cb2, lfw, lfb, lbw, lbb, XE, LP);
    dim3 g(4, 4, 64);
    k_gemm<<<g, 256, GEMM_SMEM>>>(P, P, Q, nullptr, nullptr, nullptr);
    k_gemm<<<g, 256, GEMM_SMEM>>>(Q, P, Q, P, Q, MQ);   // M -> int4 g_MQ
    k_scan<<<BSZ, 512>>>(skills, XE, LP, MQ, (float*)d_out);
}

// round 15
// speedup vs baseline: 1.4259x; 1.4259x over previous
#include <cuda_runtime.h>
#include <cuda_bf16.h>
#include <cuda_fp16.h>
#include <mma.h>
using namespace nvcuda;

#define NN  512
#define BSZ 64
#define TT  200

#define QM4  2560.0f
#define QL0  7.0f
#define QL1  127.0f

static constexpr size_t MAT = (size_t)BSZ * NN * NN;
__device__ __nv_bfloat16 g_P[MAT];
__device__ __nv_bfloat16 g_Q[MAT];
__device__ unsigned char g_MQ[(size_t)BSZ * NN * 256];   // int4-packed M^T

// ---------------------------------------------------------------------------
__global__ void k_convert(const float* __restrict__ adj, __nv_bfloat16* __restrict__ P) {
    size_t i = ((size_t)blockIdx.x * blockDim.x + threadIdx.x) * 4;
    float4 v = *(const float4*)(adj + i);
    const float s = 1.0f / 512.0f;
    __nv_bfloat162 p0 = __floats2bfloat162_rn(v.x * s, v.y * s);
    __nv_bfloat162 p1 = __floats2bfloat162_rn(v.z * s, v.w * s);
    uint2 u; u.x = *(unsigned*)&p0; u.y = *(unsigned*)&p1;
    *(uint2*)(P + i) = u;
}

__device__ __forceinline__ float2 bf2f2(unsigned u) {
    __nv_bfloat162 h = *(__nv_bfloat162*)&u;
    return make_float2(__low2float(h), __high2float(h));
}

__device__ __forceinline__ void cp16(void* s, const void* g) {
    unsigned sa = (unsigned)__cvta_generic_to_shared(s);
    asm volatile("cp.async.cg.shared.global [%0], [%1], 16;\n" :: "r"(sa), "l"(g));
}

// Batched bf16 GEMM, 3-stage cp.async pipeline, padded smem.
// qOut == null: C = A@B (bf16 write).
// qOut != null: M = A@B + addA + addB, quantized int4-packed transposed into qOut.
#define AST 72
#define BST 136
#define A_ELL (128 * AST)
#define B_ELL (64 * BST)
#define STG_ELL (A_ELL + B_ELL)
#define GEMM_SMEM (3 * STG_ELL * 2)

__global__ void __launch_bounds__(256) k_gemm(const __nv_bfloat16* __restrict__ A,
                                              const __nv_bfloat16* __restrict__ B,
                                              __nv_bfloat16* __restrict__ C,
                                              const __nv_bfloat16* __restrict__ addA,
                                              const __nv_bfloat16* __restrict__ addB,
                                              unsigned char* __restrict__ qOut) {
    extern __shared__ __nv_bfloat16 smg[];
    const int tid = threadIdx.x, b = blockIdx.z;
    const int bm0 = blockIdx.y * 128, bn0 = blockIdx.x * 128;
    const __nv_bfloat16* Ab = A + (size_t)b * NN * NN;
    const __nv_bfloat16* Bb = B + (size_t)b * NN * NN;
    const int ar = tid >> 3, ac = (tid & 7) * 8;
    const int br = tid >> 4, bc = (tid & 15) * 8;
    auto load_tiles = [&](int st, int k0) {
        __nv_bfloat16* a  = smg + st * STG_ELL;
        __nv_bfloat16* bt = smg + st * STG_ELL + A_ELL;
#pragma unroll
        for (int rr = 0; rr < 128; rr += 32)
            cp16(a + (ar + rr) * AST + ac, Ab + (size_t)(bm0 + ar + rr) * NN + k0 + ac);
#pragma unroll
        for (int rr = 0; rr < 64; rr += 16)
            cp16(bt + (br + rr) * BST + bc, Bb + (size_t)(k0 + br + rr) * NN + bn0 + bc);
        asm volatile("cp.async.commit_group;\n");
    };
    const int w = tid >> 5, wm = w >> 1, wn = w & 1;
    wmma::fragment<wmma::accumulator, 16, 16, 16, float> cf[2][4];
#pragma unroll
    for (int i = 0; i < 2; i++)
#pragma unroll
        for (int j = 0; j < 4; j++) wmma::fill_fragment(cf[i][j], 0.0f);
    load_tiles(0, 0);
    load_tiles(1, 64);
#pragma unroll
    for (int kt = 0; kt < 8; ++kt) {
        if (kt < 6) asm volatile("cp.async.wait_group 1;\n");
        else        asm volatile("cp.async.wait_group 0;\n");
        __syncthreads();
        if (kt < 6) load_tiles((kt + 2) % 3, (kt + 2) * 64);
        const __nv_bfloat16* a  = smg + (kt % 3) * STG_ELL;
        const __nv_bfloat16* bt = smg + (kt % 3) * STG_ELL + A_ELL;
#pragma unroll
        for (int kk = 0; kk < 4; ++kk) {
            wmma::fragment<wmma::matrix_a, 16, 16, 16, __nv_bfloat16, wmma::row_major> af[2];
            wmma::fragment<wmma::matrix_b, 16, 16, 16, __nv_bfloat16, wmma::row_major> bfr[4];
#pragma unroll
            for (int i = 0; i < 2; i++)
                wmma::load_matrix_sync(af[i], a + (wm * 32 + i * 16) * AST + kk * 16, AST);
#pragma unroll
            for (int j = 0; j < 4; j++)
                wmma::load_matrix_sync(bfr[j], bt + (kk * 16) * BST + wn * 64 + j * 16, BST);
#pragma unroll
            for (int i = 0; i < 2; i++)
#pragma unroll
                for (int j = 0; j < 4; j++)
                    wmma::mma_sync(cf[i][j], af[i], bfr[j], cf[i][j]);
        }
    }
    __syncthreads();
    float* Cs = (float*)smg;
#pragma unroll
    for (int i = 0; i < 2; i++)
#pragma unroll
        for (int j = 0; j < 4; j++)
            wmma::store_matrix_sync(Cs + (wm * 32 + i * 16) * 132 + wn * 64 + j * 16,
                                    cf[i][j], 132, wmma::mem_row_major);
    __syncthreads();

    const int rl = tid >> 1, half = tid & 1;
    const size_t goff = (size_t)b * NN * NN + (size_t)(bm0 + rl) * NN + bn0 + half * 64;

    if (qOut == nullptr) {
        __nv_bfloat16* Cg = C + goff;
        const float* src = Cs + rl * 132 + half * 64;
#pragma unroll
        for (int c = 0; c < 64; c += 4) {
            float4 v = *(const float4*)(src + c);
            __nv_bfloat162 p0 = __floats2bfloat162_rn(v.x, v.y);
            __nv_bfloat162 p1 = __floats2bfloat162_rn(v.z, v.w);
            uint2 u; u.x = *(unsigned*)&p0; u.y = *(unsigned*)&p1;
            *(uint2*)(Cg + c) = u;
        }
        return;
    }

    // fused M = acc + addA + addB (in place), then int4-pack transposed
    {
        float* dst = Cs + rl * 132 + half * 64;
#pragma unroll
        for (int c = 0; c < 64; c += 4) {
            float4 v = *(const float4*)(dst + c);
            uint2 pa = *(const uint2*)(addA + goff + c);
            uint2 qa = *(const uint2*)(addB + goff + c);
            float2 a0 = bf2f2(pa.x), a1 = bf2f2(pa.y);
            float2 b0 = bf2f2(qa.x), b1 = bf2f2(qa.y);
            v.x += a0.x + b0.x; v.y += a0.y + b0.y;
            v.z += a1.x + b1.x; v.w += a1.y + b1.y;
            *(float4*)(dst + c) = v;
        }
    }
    __syncthreads();
    {
        const int kr = tid >> 1;
        const int jh = (tid & 1) * 32;
        unsigned char bytes[32];
#pragma unroll
        for (int jj = 0; jj < 32; ++jj) {
            const int jp = jh + jj;
            float v0 = Cs[(2 * jp) * 132 + kr];
            float v1 = Cs[(2 * jp + 1) * 132 + kr];
            int q0 = min(15, max(0, __float2int_rn(v0 * QM4)));
            int q1 = min(15, max(0, __float2int_rn(v1 * QM4)));
            bytes[jj] = (unsigned char)(q0 | (q1 << 4));
        }
        unsigned char* dst = qOut + (size_t)b * (NN * 256) + (size_t)(bn0 + kr) * 256 + (bm0 >> 1) + jh;
        *(uint4*)(dst)      = *(uint4*)(bytes);
        *(uint4*)(dst + 16) = *(uint4*)(bytes + 16);
    }
}

// ---------------------------------------------------------------------------
// Single-CTA scan: one CTA per batch, 640 threads.
// Full M as int4 nibbles in SMEM (copied from pre-packed g_MQ).
// ---------------------------------------------------------------------------
#define MROW 272
#define OFF_MQ     0
#define OFF_LPQ    139264
#define OFF_W1     140288
#define OFF_W2     160768
#define OFF_WF     164864
#define OFF_WB     168960
#define OFF_BIAS   173056
#define OFF_UB     173568
#define OFF_UF     173824
#define OFF_H      174080
#define OFF_UU     174208
#define OFF_MLPP   174336
#define OFF_SKC    174848
#define OFF_DEL    175104
#define OFF_LAB    175904
#define OFF_SKL    176704
#define SCAN_SMEM  177536

__device__ __forceinline__ unsigned long long packf2(float lo, float hi) {
    unsigned long long r;
    asm("mov.b64 %0, {%1, %2};" : "=l"(r) : "f"(lo), "f"(hi));
    return r;
}
__device__ __forceinline__ void fma_x2(unsigned long long& acc, unsigned long long a, unsigned long long b) {
    asm("fma.rn.f32x2 %0, %1, %2, %0;" : "+l"(acc) : "l"(a), "l"(b));
}
__device__ __forceinline__ float2 unpackf2(unsigned long long v) {
    float lo, hi;
    asm("mov.b64 {%0, %1}, %2;" : "=f"(lo), "=f"(hi) : "l"(v));
    return make_float2(lo, hi);
}
__device__ __forceinline__ void dp4aUS(int& acc, unsigned a, unsigned b) {
    asm("dp4a.u32.s32 %0, %1, %2, %0;" : "+r"(acc) : "r"(a), "r"(b));
}
#define BAR1() asm volatile("bar.sync 1, 128;" ::: "memory")

__global__ void __launch_bounds__(640, 1)
k_scan(const int* __restrict__ skills, const int* __restrict__ times_,
       const float* __restrict__ labels, const float* __restrict__ nemb,
       const float* __restrict__ ub0, const float* __restrict__ uf0,
       const float* __restrict__ cw1, const float* __restrict__ cb1,
       const float* __restrict__ cw2, const float* __restrict__ cb2,
       const float* __restrict__ lfw, const float* __restrict__ lfb,
       const float* __restrict__ lbw, const float* __restrict__ lbb,
       const unsigned char* __restrict__ MQg, float* __restrict__ out) {

    extern __shared__ char smb[];
    char*   mq    = smb + OFF_MQ;
    char*   lpq   = smb + OFF_LPQ;
    float*  w1t   = (float*)(smb + OFF_W1);
    float*  w2t   = (float*)(smb + OFF_W2);
    float*  wft   = (float*)(smb + OFF_WF);
    float*  wbt   = (float*)(smb + OFF_WB);
    float*  bias  = (float*)(smb + OFF_BIAS);
    float*  ubuf  = (float*)(smb + OFF_UB);
    float*  ufbuf = (float*)(smb + OFF_UF);
    float*  hbuf  = (float*)(smb + OFF_H);
    float*  uubuf = (float*)(smb + OFF_UU);
    float*  mlpp  = (float*)(smb + OFF_MLPP);
    float*  skc   = (float*)(smb + OFF_SKC);
    float*  del_s = (float*)(smb + OFF_DEL);
    float*  lab_s = (float*)(smb + OFF_LAB);
    int*    skl_s = (int*)(smb + OFF_SKL);

    const int tid = threadIdx.x;
    const int b   = blockIdx.x;

    for (int i = tid; i < 5120; i += 640) { int o = i / 160, r = i % 160; w1t[r * 32 + o] = cw1[i]; }
    for (int i = tid; i < 1024; i += 640) {
        int o = i >> 5, r = i & 31;
        w2t[r * 32 + o] = cw2[i]; wft[r * 32 + o] = lfw[i]; wbt[r * 32 + o] = lbw[i];
    }
    if (tid < 32) {
        bias[tid] = cb1[tid]; bias[32 + tid] = cb2[tid];
        bias[64 + tid] = lfb[tid]; bias[96 + tid] = lbb[tid];
        ubuf[tid] = ub0[b * 32 + tid]; ufbuf[tid] = uf0[b * 32 + tid];
    }
    const float invlog5 = 0.6213349345596119f;
    for (int s = tid; s < TT - 1; s += 640) {
        float dtv = fabsf((float)(times_[b * TT + s + 1] - times_[b * TT + s]));
        del_s[s] = logf(dtv + 1e-6f) * invlog5;
        lab_s[s] = labels[b * TT + s + 1];
        skl_s[s] = skills[b * TT + s + 1];
    }

    unsigned long long nr2[16], ns2[16];
    if (tid < 512) {
#pragma unroll
        for (int i = 0; i < 16; i++) {
            float2 s2 = *(const float2*)(nemb + tid * 64 + 2 * i);
            float2 r2 = *(const float2*)(nemb + tid * 64 + 32 + 2 * i);
            ns2[i] = packf2(s2.x, s2.y);
            nr2[i] = packf2(r2.x, r2.y);
        }
    }

    // int4 M fill: straight copy from pre-packed g_MQ
    {
        const uint4* MQb = (const uint4*)(MQg + (size_t)b * (NN * 256));
        for (int idx = tid; idx < 8192; idx += 640) {
            const int k = idx >> 4, c = idx & 15;
            ((uint4*)(mq + k * MROW))[c] = MQb[k * 16 + c];
        }
    }
    __syncthreads();

    float lp_reg = 0.f, nlf_reg = 0.f;
    if (tid < 512) {
        unsigned long long aB = 0ull, aN = 0ull;
        const float2* u2 = (const float2*)ubuf;
        const float2* f2 = (const float2*)ufbuf;
#pragma unroll
        for (int i = 0; i < 16; i++) {
            float2 uu2 = u2[i], ff2 = f2[i];
            fma_x2(aB, packf2(uu2.x, uu2.y), nr2[i]);
            fma_x2(aN, packf2(ff2.x, ff2.y), ns2[i]);
        }
        float2 rb = unpackf2(aB), rn = unpackf2(aN);
        lp_reg  = rb.x + rb.y;
        nlf_reg = rn.x + rn.y;
        int q = __float2int_rn(lp_reg * QL0);
        q = max(min(q, 127), -127);
        lpq[(tid >> 1) + (tid & 1) * 256] = (char)q;
    }
    __syncthreads();

    const float INV0 = 1.0f / (QM4 * QL0 * 1536.0f);
    const float INV1 = 1.0f / (QM4 * QL1 * 1536.0f);

    for (int s = 0; s < TT - 1; ++s) {
        const int p = s & 1;
        const int skill = skl_s[s];

        if (tid < 512) {
            unsigned long long aB = 0ull, aN = 0ull;
            const float2* u2 = (const float2*)(ubuf + p * 32);
            const float2* f2 = (const float2*)(ufbuf + p * 32);
#pragma unroll
            for (int i = 0; i < 16; i++) {
                float2 uu2 = u2[i], ff2 = f2[i];
                fma_x2(aB, packf2(uu2.x, uu2.y), nr2[i]);
                fma_x2(aN, packf2(ff2.x, ff2.y), ns2[i]);
            }
            float2 rb = unpackf2(aB), rn = unpackf2(aN);
            const float bt = rb.x + rb.y + __expf(-del_s[s] * 0.1f * nlf_reg) * lp_reg;
            nlf_reg = rn.x + rn.y;

            int aL0 = 0, aL1 = 0, aH0 = 0, aH1 = 0;
            const uint4* mp4 = (const uint4*)(mq + tid * MROW);
            const uint4* le4 = (const uint4*)(lpq + p * 512);
            const uint4* lo4 = (const uint4*)(lpq + p * 512 + 256);
#pragma unroll
            for (int i = 0; i < 16; i++) {
                uint4 m  = mp4[i];
                uint4 ea = le4[i];
                uint4 ob = lo4[i];
                dp4aUS(aL0, m.x & 0x0F0F0F0Fu, ea.x); dp4aUS(aH0, m.x & 0xF0F0F0F0u, ob.x);
                dp4aUS(aL1, m.y & 0x0F0F0F0Fu, ea.y); dp4aUS(aH1, m.y & 0xF0F0F0F0u, ob.y);
                dp4aUS(aL0, m.z & 0x0F0F0F0Fu, ea.z); dp4aUS(aH0, m.z & 0xF0F0F0F0u, ob.z);
                dp4aUS(aL1, m.w & 0x0F0F0F0Fu, ea.w); dp4aUS(aH1, m.w & 0xF0F0F0F0u, ob.w);
            }
            const int acc = (aL0 + aL1) + ((aH0 + aH1) >> 4);

            const float INVs = (s == 0) ? INV0 : INV1;
            const float x = bt + (float)acc * INVs;
            const float cur = 1.0f / (1.0f + __expf(-x));
            lp_reg = cur;
            if (tid == skill) out[s * BSZ + b] = cur;
            const int q8 = __float2int_rn(cur * QL1);
            lpq[(p ^ 1) * 512 + (tid >> 1) + (tid & 1) * 256] = (char)q8;
        } else {
            const int m = tid - 512;
            const int o = m & 31;
            const float lab = lab_s[s];
            if (m < 64) skc[m] = __ldg(nemb + skill * 64 + m);
            BAR1();
            {
                const int q = m >> 5;
                float hp = 0.f;
#pragma unroll
                for (int cc = 0; cc < 8; cc++) {
                    const int c = q * 8 + cc;
                    const float u0 = ubuf[p * 32 + c], u1 = ufbuf[p * 32 + c];
                    const float u3 = skc[32 + c], u4 = skc[c];
                    const float* wv = w1t + c * 160 + o;
                    hp += u0 * wv[0] + u1 * wv[32] + lab * wv[64] + u3 * wv[96] + u4 * wv[128];
                }
                mlpp[q * 32 + o] = hp;
            }
            BAR1();
            if (m < 32) hbuf[o] = fmaxf(bias[o] + mlpp[o] + mlpp[32 + o] + mlpp[64 + o] + mlpp[96 + o], 0.f);
            BAR1();
            {
                const int q = m >> 5;
                float up = 0.f;
#pragma unroll
                for (int ii = 0; ii < 8; ii++) {
                    const int i2 = q * 8 + ii;
                    up += hbuf[i2] * w2t[i2 * 32 + o];
                }
                mlpp[q * 32 + o] = up;
            }
            BAR1();
            if (m < 32) uubuf[o] = bias[32 + o] + mlpp[o] + mlpp[32 + o] + mlpp[64 + o] + mlpp[96 + o];
            BAR1();
            {
                float ap = 0.f;
                if (m < 64) {
                    const int q2 = m >> 5;
#pragma unroll
                    for (int ii = 0; ii < 16; ii++) {
                        const int i2 = q2 * 16 + ii;
                        ap += uubuf[i2] * wft[i2 * 32 + o];
                    }
                    mlpp[q2 * 32 + o] = ap;
                } else {
                    const int q2 = (m - 64) >> 5;
#pragma unroll
                    for (int ii = 0; ii < 16; ii++) {
                        const int i2 = q2 * 16 + ii;
                        ap += uubuf[i2] * wbt[i2 * 32 + o];
                    }
                    mlpp[64 + q2 * 32 + o] = ap;
                }
            }
            BAR1();
            if (m < 32) {
                ufbuf[(p ^ 1) * 32 + o] = tanhf(bias[64 + o] + mlpp[o] + mlpp[32 + o]);
                ubuf[(p ^ 1) * 32 + o]  = tanhf(bias[96 + o] + mlpp[64 + o] + mlpp[96 + o]);
            }
        }
        __syncthreads();
    }
}

// ---------------------------------------------------------------------------
extern "C" void kernel_launch(void* const* d_in, const int* in_sizes, int n_in,
                              void* d_out, int out_size) {
    const int*   skills = (const int*)  d_in[0];
    const int*   times_ = (const int*)  d_in[1];
    const float* labels = (const float*)d_in[2];
    const float* adj    = (const float*)d_in[3];
    const float* nemb   = (const float*)d_in[4];
    const float* ub0    = (const float*)d_in[5];
    const float* uf0    = (const float*)d_in[6];
    const float* cw1    = (const float*)d_in[7];
    const float* cb1    = (const float*)d_in[8];
    const float* cw2    = (const float*)d_in[9];
    const float* cb2    = (const float*)d_in[10];
    const float* lfw    = (const float*)d_in[11];
    const float* lfb    = (const float*)d_in[12];
    const float* lbw    = (const float*)d_in[13];
    const float* lbb    = (const float*)d_in[14];

    void *pP = nullptr, *pQ = nullptr, *pMQ = nullptr;
    cudaGetSymbolAddress(&pP, g_P);
    cudaGetSymbolAddress(&pQ, g_Q);
    cudaGetSymbolAddress(&pMQ, g_MQ);
    __nv_bfloat16* P  = (__nv_bfloat16*)pP;
    __nv_bfloat16* Q  = (__nv_bfloat16*)pQ;
    unsigned char* MQ = (unsigned char*)pMQ;

    cudaFuncSetAttribute(k_gemm, cudaFuncAttributeMaxDynamicSharedMemorySize, GEMM_SMEM);
    cudaFuncSetAttribute(k_scan, cudaFuncAttributeMaxDynamicSharedMemorySize, SCAN_SMEM);

    k_convert<<<16384, 256>>>(adj, P);
    dim3 g(4, 4, 64);
    k_gemm<<<g, 256, GEMM_SMEM>>>(P, P, Q, nullptr, nullptr, nullptr);
    // M = Q@P + P + Q, quantized int4 transposed directly into g_MQ
    k_gemm<<<g, 256, GEMM_SMEM>>>(Q, P, Q, P, Q, MQ);
    k_scan<<<BSZ, 640, SCAN_SMEM>>>(skills, times_, labels, nemb, ub0, uf0,
                                    cw1, cb1, cw2, cb2, lfw, lfb, lbw, lbb,
                                    MQ, (float*)d_out);
}